// round 9
// baseline (speedup 1.0000x reference)
#include <cuda_runtime.h>
#include <cuda_bf16.h>
#include <math.h>

#define BATCH  1024
#define SEQN   128
#define DMODEL 256
#define NROWS  (BATCH*SEQN)            // 131072
#define ELEMS  (BATCH*SEQN*DMODEL)     // 33554432
#define SST    132                     // padded smem row stride (floats)

// bf16 GEMM smem layout, u32 units. Row stride = 20 u32 (32 bf16 + pad) = 80 B.
#define RSTR 20
#define UA_H 0
#define UA_L (128*RSTR)
#define UB_H (2*128*RSTR)
#define UB_L (3*128*RSTR)
#define SM_GEMM_U32 (4*128*RSTR)     // 10240 u32 = 40960 B

// packed activation row stride (u32) = 128 (256 bf16 values / 2)
#define PKL 128

// weight pack offsets (u32) in g_WH/g_WL
#define WO_SAQ  0
#define WO_SAK  32768
#define WO_SAV  65536
#define WO_SAF  98304
#define WO_MS1  131072   // 256 n x 192 kp
#define WO_MS2  180224
#define WO_CAQ  212992
#define WO_CAK  245760
#define WO_CAV  278528
#define W_TOTAL 311296

// ---------------- scratch ----------------
__device__ float g_KV[ELEMS];
__device__ float g_Q [ELEMS];
__device__ float g_K [ELEMS];
__device__ float g_V [ELEMS];
__device__ float g_FC[ELEMS];
__device__ float g_KH[ELEMS];
__device__ float g_VH[ELEMS];
__device__ float g_QH[BATCH*DMODEL];
__device__ unsigned g_KVh[NROWS*PKL];
__device__ unsigned g_KVl[NROWS*PKL];
__device__ unsigned g_AOh[NROWS*PKL];
__device__ unsigned g_AOl[NROWS*PKL];
__device__ unsigned g_SAh[NROWS*PKL];
__device__ unsigned g_SAl[NROWS*PKL];
__device__ unsigned g_H1h[NROWS*PKL];
__device__ unsigned g_H1l[NROWS*PKL];
__device__ unsigned g_KCh[NROWS*PKL];
__device__ unsigned g_KCl[NROWS*PKL];
__device__ unsigned g_SRCh[BATCH*PKL];
__device__ unsigned g_SRCl[BATCH*PKL];
__device__ unsigned g_WH[W_TOTAL];
__device__ unsigned g_WL[W_TOTAL];
__device__ unsigned char g_mask8[NROWS];
__device__ int g_mask_mode;

// ---------------- bf16 helpers ----------------
__device__ __forceinline__ unsigned pack_bf16x2(float lo, float hi) {
    unsigned r;
    asm("cvt.rn.bf16x2.f32 %0, %1, %2;" : "=r"(r) : "f"(hi), "f"(lo));
    return r;
}
__device__ __forceinline__ float lo_bf16f(unsigned u) { return __uint_as_float(u << 16); }
__device__ __forceinline__ float hi_bf16f(unsigned u) { return __uint_as_float(u & 0xFFFF0000u); }

// split pair (f0,f1) -> hi word + lo(residual) word
__device__ __forceinline__ void split_pair(float f0, float f1, unsigned& h, unsigned& l) {
    h = pack_bf16x2(f0, f1);
    l = pack_bf16x2(f0 - lo_bf16f(h), f1 - hi_bf16f(h));
}

__device__ __forceinline__ void mma_bf16(float* d, const unsigned* a, const unsigned* b) {
    asm volatile(
        "mma.sync.aligned.m16n8k16.row.col.f32.bf16.bf16.f32 "
        "{%0,%1,%2,%3}, {%4,%5,%6,%7}, {%8,%9}, {%0,%1,%2,%3};\n"
        : "+f"(d[0]), "+f"(d[1]), "+f"(d[2]), "+f"(d[3])
        : "r"(a[0]), "r"(a[1]), "r"(a[2]), "r"(a[3]),
          "r"(b[0]), "r"(b[1]));
}

// ---------------- tf32 helpers (sa_attn S phase) ----------------
__device__ __forceinline__ unsigned cvt_tf32(float x) {
    unsigned u;
    asm("cvt.rna.tf32.f32 %0, %1;" : "=r"(u) : "f"(x));
    return u;
}
__device__ __forceinline__ void split_tf32(float x, unsigned& hi, unsigned& lo) {
    hi = cvt_tf32(x);
    lo = cvt_tf32(x - __uint_as_float(hi));
}
__device__ __forceinline__ void mma_tf32(float* d, const unsigned* a, const unsigned* b) {
    asm volatile(
        "mma.sync.aligned.m16n8k8.row.col.f32.tf32.tf32.f32 "
        "{%0,%1,%2,%3}, {%4,%5,%6,%7}, {%8,%9}, {%0,%1,%2,%3};\n"
        : "+f"(d[0]), "+f"(d[1]), "+f"(d[2]), "+f"(d[3])
        : "r"(a[0]), "r"(a[1]), "r"(a[2]), "r"(a[3]),
          "r"(b[0]), "r"(b[1]));
}

// ---------------- mask dtype detection + normalization ----------------
__global__ void detect_mask_kernel(const void* mask) {
    if (threadIdx.x == 0 && blockIdx.x == 0) {
        const unsigned* p = (const unsigned*)mask;
        int mode = 1;
        for (int i = 0; i < 1024; i++) {
            unsigned v = p[i];
            if (v == 0x3F800000u) { mode = 2; break; }
            if (v > 1u) { mode = 0; break; }
        }
        g_mask_mode = mode;
    }
}

__global__ __launch_bounds__(256) void norm_mask_kernel(const void* mask) {
    int i = blockIdx.x * 256 + threadIdx.x;
    if (i >= NROWS) return;
    int mode = g_mask_mode;
    unsigned char m;
    if (mode == 0)      m = (((const unsigned char*)mask)[i] != 0);
    else if (mode == 1) m = (((const int*)mask)[i] != 0);
    else                m = (((const float*)mask)[i] != 0.f);
    g_mask8[i] = m;
}

// ---------------- weight pack: W[Kt,N] -> [n][kp] hi/lo ----------------
__global__ __launch_bounds__(256) void pack_w_kernel(
    const float* __restrict__ W, int Kt, int N,
    unsigned* __restrict__ oh, unsigned* __restrict__ ol)
{
    int idx = blockIdx.x * 256 + threadIdx.x;
    int khalf = Kt >> 1;
    if (idx >= N * khalf) return;
    int n = idx / khalf, kp = idx - n * khalf;
    float f0 = W[(2 * kp) * N + n];
    float f1 = W[(2 * kp + 1) * N + n];
    unsigned h, l;
    split_pair(f0, f1, h, l);
    oh[idx] = h;
    ol[idx] = l;
}

// ---------------- src pack: concat(src,srct)[b][256] -> [b][kp] ----------------
__global__ __launch_bounds__(256) void pack_src_kernel(
    const float* __restrict__ src, const float* __restrict__ srct)
{
    int idx = blockIdx.x * 256 + threadIdx.x;
    if (idx >= BATCH * PKL) return;
    int b = idx >> 7, kp = idx & 127;
    float f0, f1;
    if (kp < 64) { f0 = src [b * 128 + 2 * kp];        f1 = src [b * 128 + 2 * kp + 1]; }
    else         { f0 = srct[b * 128 + 2 * (kp - 64)]; f1 = srct[b * 128 + 2 * (kp - 64) + 1]; }
    unsigned h, l;
    split_pair(f0, f1, h, l);
    g_SRCh[idx] = h;
    g_SRCl[idx] = l;
}

// ---------------- concat([seq, seq_t]) -> KV fp32 + KV packed ----------------
__global__ __launch_bounds__(256) void concat_kv_kernel(
    const float* __restrict__ seq, const float* __restrict__ seqt)
{
    long i4 = (long)blockIdx.x * 256 + threadIdx.x;
    if (i4 >= (long)ELEMS / 4) return;
    long row = i4 >> 6;
    int  c4  = (int)(i4 & 63);
    float4 v;
    if (c4 < 32) v = ((const float4*)(seq  + row * 128))[c4];
    else         v = ((const float4*)(seqt + row * 128))[c4 - 32];
    ((float4*)(g_KV + row * 256))[c4] = v;
    unsigned h0, l0, h1, l1;
    split_pair(v.x, v.y, h0, l0);
    split_pair(v.z, v.w, h1, l1);
    long pi = row * PKL + c4 * 2;
    *(uint2*)&g_KVh[pi] = make_uint2(h0, h1);
    *(uint2*)&g_KVl[pi] = make_uint2(l0, l1);
}

// ---------------- 3xBF16 GEMM with pre-packed operands ----------------
// A packed [m][kp] (dual source split at K1p), W packed [n][kp].
// Outputs: C fp32 (optional) and/or packed hi/lo (optional).
__global__ __launch_bounds__(256, 2) void gemm_tc_kernel(
    const unsigned* __restrict__ A1h, const unsigned* __restrict__ A1l, int K1p, int lda1p,
    const unsigned* __restrict__ A2h, const unsigned* __restrict__ A2l, int lda2p,
    const unsigned* __restrict__ Wh, const unsigned* __restrict__ Wl, int Ktot, int Ncols,
    const float* __restrict__ bias,
    const float* __restrict__ res,
    int relu,
    float* __restrict__ C,
    unsigned* __restrict__ Cph, unsigned* __restrict__ Cpl)
{
    extern __shared__ unsigned su[];
    unsigned* sAh = su + UA_H;
    unsigned* sAl = su + UA_L;
    unsigned* sBh = su + UB_H;
    unsigned* sBl = su + UB_L;

    const int tid  = threadIdx.x;
    const int warp = tid >> 5, lane = tid & 31;
    const int wm = warp & 3, wn = warp >> 2;
    const int group = lane >> 2, tig = lane & 3;
    const long m0 = (long)blockIdx.y * 128;
    const int  n0 = blockIdx.x * 128;
    const int wmb = wm * 32;
    const int wnb = wn * 64;
    const int khalf = Ktot >> 1;

    float acc[2][8][4];
#pragma unroll
    for (int mi = 0; mi < 2; mi++)
#pragma unroll
        for (int ni = 0; ni < 8; ni++)
#pragma unroll
            for (int q = 0; q < 4; q++) acc[mi][ni][q] = 0.f;

    const int nk = Ktot / 32;

    for (int ck = 0; ck < nk; ck++) {
        const int k0p = ck * 16;           // u32 offset of chunk
        if (ck > 0) __syncthreads();

        // ---- stage A: 128 rows x 16 u32 ----
#pragma unroll
        for (int i = 0; i < 4; i++) {
            int f4 = tid + i * 256;
            int row = f4 >> 3, cu = (f4 & 7) * 2;
            int kp = k0p + cu;
            uint2 h, l;
            if (kp < K1p) {
                long idx = (m0 + row) * (long)lda1p + kp;
                h = *(const uint2*)&A1h[idx];
                l = *(const uint2*)&A1l[idx];
            } else {
                long idx = (m0 + row) * (long)lda2p + (kp - K1p);
                h = *(const uint2*)&A2h[idx];
                l = *(const uint2*)&A2l[idx];
            }
            int ui = row * RSTR + cu;
            *(uint2*)&sAh[ui] = h;
            *(uint2*)&sAl[ui] = l;
        }
        // ---- stage B: 128 n-rows x 16 u32 ----
#pragma unroll
        for (int i = 0; i < 4; i++) {
            int task = tid + i * 256;
            int kq = task & 7;             // 2 u32 each
            int n  = task >> 3;
            long wi = (long)(n0 + n) * khalf + k0p + kq * 2;
            uint2 h = *(const uint2*)&Wh[wi];
            uint2 l = *(const uint2*)&Wl[wi];
            int ui = n * RSTR + kq * 2;
            *(uint2*)&sBh[ui] = h;
            *(uint2*)&sBl[ui] = l;
        }
        __syncthreads();

        // ---- compute: identical to proven R8 loop ----
#pragma unroll
        for (int ks = 0; ks < 2; ks++) {
            const int kb8 = ks * 8;
            unsigned ah[2][4], al[2][4];
#pragma unroll
            for (int mi = 0; mi < 2; mi++) {
                int r = wmb + mi * 16 + group;
                int i0 = r * RSTR + kb8 + tig;
                int i1 = (r + 8) * RSTR + kb8 + tig;
                ah[mi][0] = sAh[i0];
                ah[mi][1] = sAh[i1];
                ah[mi][2] = sAh[i0 + 4];
                ah[mi][3] = sAh[i1 + 4];
                al[mi][0] = sAl[i0];
                al[mi][1] = sAl[i1];
                al[mi][2] = sAl[i0 + 4];
                al[mi][3] = sAl[i1 + 4];
            }
#pragma unroll
            for (int nt = 0; nt < 8; nt++) {
                int nrow = wnb + nt * 8 + group;
                int bi = nrow * RSTR + kb8 + tig;
                unsigned bh[2], bl[2];
                bh[0] = sBh[bi];
                bh[1] = sBh[bi + 4];
                bl[0] = sBl[bi];
                bl[1] = sBl[bi + 4];
#pragma unroll
                for (int mi = 0; mi < 2; mi++) {
                    mma_bf16(acc[mi][nt], ah[mi], bh);
                    mma_bf16(acc[mi][nt], al[mi], bh);
                    mma_bf16(acc[mi][nt], ah[mi], bl);
                }
            }
        }
    }

    // ---- epilogue ----
    const int nhalf = Ncols >> 1;
#pragma unroll
    for (int mi = 0; mi < 2; mi++) {
        long gm = m0 + wmb + mi * 16 + group;
#pragma unroll
        for (int ni = 0; ni < 8; ni++) {
            int gc = n0 + wnb + ni * 8 + 2 * tig;
            float v0 = acc[mi][ni][0], v1 = acc[mi][ni][1];
            float v2 = acc[mi][ni][2], v3 = acc[mi][ni][3];
            if (bias) {
                float b0 = bias[gc], b1 = bias[gc + 1];
                v0 += b0; v1 += b1; v2 += b0; v3 += b1;
            }
            if (res) {
                float2 r0 = *(const float2*)(res + gm * Ncols + gc);
                float2 r1 = *(const float2*)(res + (gm + 8) * Ncols + gc);
                v0 += r0.x; v1 += r0.y; v2 += r1.x; v3 += r1.y;
            }
            if (relu) {
                v0 = fmaxf(v0, 0.f); v1 = fmaxf(v1, 0.f);
                v2 = fmaxf(v2, 0.f); v3 = fmaxf(v3, 0.f);
            }
            if (C) {
                *(float2*)(C + gm * Ncols + gc)       = make_float2(v0, v1);
                *(float2*)(C + (gm + 8) * Ncols + gc) = make_float2(v2, v3);
            }
            if (Cph) {
                unsigned h0, l0, h1, l1;
                split_pair(v0, v1, h0, l0);
                split_pair(v2, v3, h1, l1);
                long p0 = gm * nhalf + (gc >> 1);
                long p1 = (gm + 8) * nhalf + (gc >> 1);
                Cph[p0] = h0; Cpl[p0] = l0;
                Cph[p1] = h1; Cpl[p1] = l1;
            }
        }
    }
}

// ---------------- self-attention: tensor-core S (tf32), FFMA O, packed AO out ----------------
__global__ __launch_bounds__(256) void sa_attn_kernel(
    const float* __restrict__ Q, const float* __restrict__ K, const float* __restrict__ V,
    const unsigned char* __restrict__ mask,
    unsigned* __restrict__ AOh, unsigned* __restrict__ AOl)
{
    extern __shared__ float sm[];
    float* sQ  = sm;
    float* sK  = sm + 128 * SST;
    float* sPt = sm + 2 * 128 * SST;
    __shared__ unsigned char smask[128];

    const int h = blockIdx.x, b = blockIdx.y;
    const int tid = threadIdx.x;
    const int warp = tid >> 5, lane = tid & 31;
    const int group = lane >> 2, tig = lane & 3;
    const float* Qp = Q + ((long)b * SEQN) * DMODEL + h * 128;
    const float* Kp = K + ((long)b * SEQN) * DMODEL + h * 128;
    const float* Vp = V + ((long)b * SEQN) * DMODEL + h * 128;
    const float invs = 0.0883883476483184f;

    if (tid < 128) smask[tid] = mask[(long)b * SEQN + tid];
    for (int idx = tid; idx < 128 * 32; idx += 256) {
        int r = idx >> 5;
        int c = (idx & 31) << 2;
        float4 qv = *(const float4*)(Qp + (long)r * DMODEL + c);
        qv.x *= invs; qv.y *= invs; qv.z *= invs; qv.w *= invs;
        *(float4*)&sQ[r * SST + c] = qv;
        *(float4*)&sK[r * SST + c] = *(const float4*)(Kp + (long)r * DMODEL + c);
    }
    __syncthreads();

    {
        const int wm = warp & 3;
        const int wmb = wm * 32, wnb = (warp >> 2) * 64;
        float acc[2][8][4];
#pragma unroll
        for (int mi = 0; mi < 2; mi++)
#pragma unroll
            for (int ni = 0; ni < 8; ni++)
#pragma unroll
                for (int q = 0; q < 4; q++) acc[mi][ni][q] = 0.f;

        for (int kb = 0; kb < 128; kb += 8) {
            unsigned af[2][4], alf[2][4];
#pragma unroll
            for (int mi = 0; mi < 2; mi++) {
                int r = wmb + mi * 16 + group;
                split_tf32(sQ[r * SST + kb + tig],           af[mi][0], alf[mi][0]);
                split_tf32(sQ[(r + 8) * SST + kb + tig],     af[mi][1], alf[mi][1]);
                split_tf32(sQ[r * SST + kb + tig + 4],       af[mi][2], alf[mi][2]);
                split_tf32(sQ[(r + 8) * SST + kb + tig + 4], af[mi][3], alf[mi][3]);
            }
#pragma unroll
            for (int j = 0; j < 8; j++) {
                int col = wnb + j * 8 + group;
                unsigned bf[2], blf[2];
                split_tf32(sK[col * SST + kb + tig],     bf[0], blf[0]);
                split_tf32(sK[col * SST + kb + tig + 4], bf[1], blf[1]);
#pragma unroll
                for (int mi = 0; mi < 2; mi++) {
                    mma_tf32(acc[mi][j], af[mi],  bf);
                    mma_tf32(acc[mi][j], alf[mi], bf);
                    mma_tf32(acc[mi][j], af[mi],  blf);
                }
            }
        }
#pragma unroll
        for (int mi = 0; mi < 2; mi++) {
            int gm0 = wmb + mi * 16 + group;
#pragma unroll
            for (int ni = 0; ni < 8; ni++) {
                int gc0 = wnb + ni * 8 + 2 * tig;
                sPt[gc0 * SST + gm0]           = acc[mi][ni][0];
                sPt[(gc0 + 1) * SST + gm0]     = acc[mi][ni][1];
                sPt[gc0 * SST + gm0 + 8]       = acc[mi][ni][2];
                sPt[(gc0 + 1) * SST + gm0 + 8] = acc[mi][ni][3];
            }
        }
    }
    __syncthreads();

    for (int idx = tid; idx < 128 * 32; idx += 256) {
        int r = idx >> 5;
        int c = (idx & 31) << 2;
        *(float4*)&sQ[r * SST + c] = *(const float4*)(Vp + (long)r * DMODEL + c);
    }
    for (int r = warp; r < 128; r += 8) {
        float vv[4];
        float mx = -1e30f;
#pragma unroll
        for (int q = 0; q < 4; q++) {
            int c = lane + q * 32;
            float s = sPt[c * SST + r];
            if (smask[c]) s = -1e10f;
            vv[q] = s; mx = fmaxf(mx, s);
        }
#pragma unroll
        for (int o = 16; o > 0; o >>= 1) mx = fmaxf(mx, __shfl_xor_sync(0xffffffffu, mx, o));
        float sum = 0.f;
#pragma unroll
        for (int q = 0; q < 4; q++) { vv[q] = expf(vv[q] - mx); sum += vv[q]; }
#pragma unroll
        for (int o = 16; o > 0; o >>= 1) sum += __shfl_xor_sync(0xffffffffu, sum, o);
        float rs = 1.f / sum;
#pragma unroll
        for (int q = 0; q < 4; q++) sPt[(lane + q * 32) * SST + r] = vv[q] * rs;
    }
    __syncthreads();

    const int tx = tid & 15, ty = tid >> 4;
    float oc[8][8];
#pragma unroll
    for (int i = 0; i < 8; i++)
#pragma unroll
        for (int j = 0; j < 8; j++) oc[i][j] = 0.f;
    for (int k = 0; k < 128; k++) {
        float a[8], bb[8];
#pragma unroll
        for (int i = 0; i < 8; i++) a[i]  = sPt[k * SST + ty * 8 + i];
#pragma unroll
        for (int j = 0; j < 8; j++) bb[j] = sQ[k * SST + tx * 8 + j];
#pragma unroll
        for (int i = 0; i < 8; i++)
#pragma unroll
            for (int j = 0; j < 8; j++)
                oc[i][j] = fmaf(a[i], bb[j], oc[i][j]);
    }
    // packed AO out: row m = b*128 + ty*8+i ; cols h*128 + tx*8 .. +7 -> kp0 = h*64 + tx*4
    const int kp0 = h * 64 + tx * 4;
#pragma unroll
    for (int i = 0; i < 8; i++) {
        long m = (long)b * SEQN + ty * 8 + i;
        unsigned hh[4], ll[4];
#pragma unroll
        for (int p = 0; p < 4; p++)
            split_pair(oc[i][2 * p], oc[i][2 * p + 1], hh[p], ll[p]);
        *(uint4*)&AOh[m * PKL + kp0] = make_uint4(hh[0], hh[1], hh[2], hh[3]);
        *(uint4*)&AOl[m * PKL + kp0] = make_uint4(ll[0], ll[1], ll[2], ll[3]);
    }
}

// ---------------- LayerNorm over 256, warp per row, packed out ----------------
__global__ __launch_bounds__(256) void ln_kernel(
    const float* __restrict__ X, const float* __restrict__ gw,
    const float* __restrict__ bw,
    unsigned* __restrict__ Yh, unsigned* __restrict__ Yl)
{
    long row = (long)blockIdx.x * 8 + (threadIdx.x >> 5);
    int lane = threadIdx.x & 31;
    const float* xp = X + row * 256 + lane * 8;
    float4 a = *(const float4*)xp;
    float4 b = *(const float4*)(xp + 4);
    float s = a.x + a.y + a.z + a.w + b.x + b.y + b.z + b.w;
#pragma unroll
    for (int o = 16; o > 0; o >>= 1) s += __shfl_xor_sync(0xffffffffu, s, o);
    float mean = s * 0.00390625f;
    float q = 0.f;
    q += (a.x - mean) * (a.x - mean); q += (a.y - mean) * (a.y - mean);
    q += (a.z - mean) * (a.z - mean); q += (a.w - mean) * (a.w - mean);
    q += (b.x - mean) * (b.x - mean); q += (b.y - mean) * (b.y - mean);
    q += (b.z - mean) * (b.z - mean); q += (b.w - mean) * (b.w - mean);
#pragma unroll
    for (int o = 16; o > 0; o >>= 1) q += __shfl_xor_sync(0xffffffffu, q, o);
    float rstd = rsqrtf(q * 0.00390625f + 1e-5f);
    int c = lane * 8;
    float4 g0 = *(const float4*)(gw + c), g1 = *(const float4*)(gw + c + 4);
    float4 b0 = *(const float4*)(bw + c), b1 = *(const float4*)(bw + c + 4);
    float y0 = (a.x - mean) * rstd * g0.x + b0.x;
    float y1 = (a.y - mean) * rstd * g0.y + b0.y;
    float y2 = (a.z - mean) * rstd * g0.z + b0.z;
    float y3 = (a.w - mean) * rstd * g0.w + b0.w;
    float y4 = (b.x - mean) * rstd * g1.x + b1.x;
    float y5 = (b.y - mean) * rstd * g1.y + b1.y;
    float y6 = (b.z - mean) * rstd * g1.z + b1.z;
    float y7 = (b.w - mean) * rstd * g1.w + b1.w;
    unsigned h0, l0, h1, l1, h2, l2, h3, l3;
    split_pair(y0, y1, h0, l0);
    split_pair(y2, y3, h1, l1);
    split_pair(y4, y5, h2, l2);
    split_pair(y6, y7, h3, l3);
    long pi = row * PKL + lane * 4;
    *(uint4*)&Yh[pi] = make_uint4(h0, h1, h2, h3);
    *(uint4*)&Yl[pi] = make_uint4(l0, l1, l2, l3);
}

// ---------------- cross-attention + fc + LN + output MLP ----------------
__global__ __launch_bounds__(256) void ca_kernel(
    const float* __restrict__ QH, const float* __restrict__ KH, const float* __restrict__ VH,
    const unsigned char* __restrict__ mask,
    const float* __restrict__ fcw, const float* __restrict__ fcb,
    const float* __restrict__ lng, const float* __restrict__ lnb,
    const float* __restrict__ src, const float* __restrict__ srct,
    const float* __restrict__ w1, const float* __restrict__ b1,
    const float* __restrict__ w2, const float* __restrict__ b2,
    float* __restrict__ out_vec, float* __restrict__ out_attn)
{
    const int b = blockIdx.x;
    const int tid = threadIdx.x;
    __shared__ float s_q[256], s_p[256], s_o[256], s_y[256], s_h[128], s_red[16];

    s_q[tid] = QH[(long)b * 256 + tid];
    __syncthreads();

    const int h = tid >> 7, k = tid & 127;
    const int lane = tid & 31, warp = tid >> 5;

    const float* krow = KH + ((long)b * 128 + k) * 256 + h * 128;
    float s = 0.f;
#pragma unroll 8
    for (int d = 0; d < 128; d += 4) {
        float4 kv = *(const float4*)(krow + d);
        s += s_q[h * 128 + d + 0] * kv.x + s_q[h * 128 + d + 1] * kv.y
           + s_q[h * 128 + d + 2] * kv.z + s_q[h * 128 + d + 3] * kv.w;
    }
    s *= 0.0883883476483184f;
    if (mask[(long)b * 128 + k]) s = -1e10f;

    float mx = s;
#pragma unroll
    for (int o = 16; o > 0; o >>= 1) mx = fmaxf(mx, __shfl_xor_sync(0xffffffffu, mx, o));
    if (lane == 0) s_red[warp] = mx;
    __syncthreads();
    mx = fmaxf(fmaxf(s_red[h * 4 + 0], s_red[h * 4 + 1]),
               fmaxf(s_red[h * 4 + 2], s_red[h * 4 + 3]));
    float e = expf(s - mx);
    float sum = e;
#pragma unroll
    for (int o = 16; o > 0; o >>= 1) sum += __shfl_xor_sync(0xffffffffu, sum, o);
    if (lane == 0) s_red[8 + warp] = sum;
    __syncthreads();
    sum = s_red[8 + h * 4 + 0] + s_red[8 + h * 4 + 1] + s_red[8 + h * 4 + 2] + s_red[8 + h * 4 + 3];
    float p = e / sum;
    s_p[tid] = p;
    out_attn[((long)h * BATCH + b) * 128 + k] = p;
    __syncthreads();

    const int d = tid & 127;
    float o = 0.f;
#pragma unroll 8
    for (int kk = 0; kk < 128; kk++)
        o += s_p[h * 128 + kk] * VH[((long)b * 128 + kk) * 256 + h * 128 + d];
    s_o[tid] = o;
    __syncthreads();

    float y = fcb[tid];
    for (int i = 0; i < 256; i++) y += s_o[i] * fcw[i * 256 + tid];
    y += (tid < 128) ? src[(long)b * 128 + tid] : srct[(long)b * 128 + tid - 128];

    float t = y;
#pragma unroll
    for (int ofs = 16; ofs > 0; ofs >>= 1) t += __shfl_xor_sync(0xffffffffu, t, ofs);
    if (lane == 0) s_red[warp] = t;
    __syncthreads();
    float mean = (s_red[0] + s_red[1] + s_red[2] + s_red[3] +
                  s_red[4] + s_red[5] + s_red[6] + s_red[7]) * 0.00390625f;
    float dv = y - mean;
    t = dv * dv;
#pragma unroll
    for (int ofs = 16; ofs > 0; ofs >>= 1) t += __shfl_xor_sync(0xffffffffu, t, ofs);
    if (lane == 0) s_red[8 + warp] = t;
    __syncthreads();
    float var = (s_red[8] + s_red[9] + s_red[10] + s_red[11] +
                 s_red[12] + s_red[13] + s_red[14] + s_red[15]) * 0.00390625f;
    float rstd = rsqrtf(var + 1e-5f);
    s_y[tid] = dv * rstd * lng[tid] + lnb[tid];
    __syncthreads();

    if (tid < 128) {
        float hh = b1[tid];
        for (int i = 0; i < 256; i++) hh += s_y[i] * w1[i * 128 + tid];
        for (int i = 0; i < 128; i++) hh += src[(long)b * 128 + i] * w1[(256 + i) * 128 + tid];
        s_h[tid] = fmaxf(hh, 0.f);
    }
    __syncthreads();
    if (tid < 128) {
        float oo = b2[tid];
        for (int i = 0; i < 128; i++) oo += s_h[i] * w2[i * 128 + tid];
        out_vec[(long)b * 128 + tid] = oo;
    }
}

// ---------------- host ----------------
static void* sym_addr(const void* s) {
    void* p = nullptr;
    cudaGetSymbolAddress(&p, s);
    return p;
}

extern "C" void kernel_launch(void* const* d_in, const int* in_sizes, int n_in,
                              void* d_out, int out_size)
{
    const float* src   = (const float*)d_in[0];
    const float* srct  = (const float*)d_in[1];
    const float* seq   = (const float*)d_in[2];
    const float* seqt  = (const float*)d_in[3];
    const void*  maskraw = d_in[4];

    const float *sa_wq, *sa_wk, *sa_wv, *sa_fcw, *sa_fcb, *sa_lng, *sa_lnb;
    const float *ms_w1, *ms_b1, *ms_w2, *ms_b2;
    const float *ca_wq, *ca_wk, *ca_wv, *ca_fcw, *ca_fcb, *ca_lng, *ca_lnb;
    const float *mg_w1, *mg_b1, *mg_w2, *mg_b2;

    bool dict_order = (in_sizes[10] == 98304);
    if (dict_order) {
        sa_wq  = (const float*)d_in[5];
        sa_wk  = (const float*)d_in[6];
        sa_wv  = (const float*)d_in[7];
        sa_fcw = (const float*)d_in[8];
        sa_fcb = (const float*)d_in[9];
        ms_w1  = (const float*)d_in[10];
        ms_b1  = (const float*)d_in[11];
        ms_w2  = (const float*)d_in[12];
        ms_b2  = (const float*)d_in[13];
        ca_wq  = (const float*)d_in[14];
        ca_wk  = (const float*)d_in[15];
        ca_wv  = (const float*)d_in[16];
        ca_fcw = (const float*)d_in[17];
        ca_fcb = (const float*)d_in[18];
        mg_w1  = (const float*)d_in[19];
        mg_b1  = (const float*)d_in[20];
        mg_w2  = (const float*)d_in[21];
        mg_b2  = (const float*)d_in[22];
        sa_lng = (const float*)d_in[23];
        sa_lnb = (const float*)d_in[24];
        ca_lng = (const float*)d_in[25];
        ca_lnb = (const float*)d_in[26];
    } else {
        sa_wq  = (const float*)d_in[5];
        sa_wk  = (const float*)d_in[6];
        sa_wv  = (const float*)d_in[7];
        sa_fcw = (const float*)d_in[8];
        sa_fcb = (const float*)d_in[9];
        sa_lng = (const float*)d_in[10];
        sa_lnb = (const float*)d_in[11];
        ms_w1  = (const float*)d_in[12];
        ms_b1  = (const float*)d_in[13];
        ms_w2  = (const float*)d_in[14];
        ms_b2  = (const float*)d_in[15];
        ca_wq  = (const float*)d_in[16];
        ca_wk  = (const float*)d_in[17];
        ca_wv  = (const float*)d_in[18];
        ca_fcw = (const float*)d_in[19];
        ca_fcb = (const float*)d_in[20];
        ca_lng = (const float*)d_in[21];
        ca_lnb = (const float*)d_in[22];
        mg_w1  = (const float*)d_in[23];
        mg_b1  = (const float*)d_in[24];
        mg_w2  = (const float*)d_in[25];
        mg_b2  = (const float*)d_in[26];
    }
    float* out = (float*)d_out;

    float* KV = (float*)sym_addr(g_KV);
    float* Qb = (float*)sym_addr(g_Q);
    float* Kb = (float*)sym_addr(g_K);
    float* Vb = (float*)sym_addr(g_V);
    float* FC = (float*)sym_addr(g_FC);
    float* KH = (float*)sym_addr(g_KH);
    float* VH = (float*)sym_addr(g_VH);
    float* QH = (float*)sym_addr(g_QH);
    unsigned* KVh = (unsigned*)sym_addr(g_KVh);
    unsigned* KVl = (unsigned*)sym_addr(g_KVl);
    unsigned* AOh = (unsigned*)sym_addr(g_AOh);
    unsigned* AOl = (unsigned*)sym_addr(g_AOl);
    unsigned* SAh = (unsigned*)sym_addr(g_SAh);
    unsigned* SAl = (unsigned*)sym_addr(g_SAl);
    unsigned* H1h = (unsigned*)sym_addr(g_H1h);
    unsigned* H1l = (unsigned*)sym_addr(g_H1l);
    unsigned* KCh = (unsigned*)sym_addr(g_KCh);
    unsigned* KCl = (unsigned*)sym_addr(g_KCl);
    unsigned* SRCh = (unsigned*)sym_addr(g_SRCh);
    unsigned* SRCl = (unsigned*)sym_addr(g_SRCl);
    unsigned* WH = (unsigned*)sym_addr(g_WH);
    unsigned* WL = (unsigned*)sym_addr(g_WL);
    unsigned char* MK = (unsigned char*)sym_addr(g_mask8);

    const int SMEM_ATTN = 3 * 128 * SST * 4;   // 202752 bytes
    cudaFuncSetAttribute(sa_attn_kernel, cudaFuncAttributeMaxDynamicSharedMemorySize, SMEM_ATTN);
    const int SMEM_GEMM = SM_GEMM_U32 * 4;     // 40960 bytes (2 CTAs/SM)
    cudaFuncSetAttribute(gemm_tc_kernel, cudaFuncAttributeMaxDynamicSharedMemorySize, SMEM_GEMM);

    detect_mask_kernel<<<1, 32>>>(maskraw);
    norm_mask_kernel<<<NROWS / 256, 256>>>(maskraw);

    // weight packing (tiny)
    pack_w_kernel<<<(256 * 128 + 255) / 256, 256>>>(sa_wq,  256, 256, WH + WO_SAQ, WL + WO_SAQ);
    pack_w_kernel<<<(256 * 128 + 255) / 256, 256>>>(sa_wk,  256, 256, WH + WO_SAK, WL + WO_SAK);
    pack_w_kernel<<<(256 * 128 + 255) / 256, 256>>>(sa_wv,  256, 256, WH + WO_SAV, WL + WO_SAV);
    pack_w_kernel<<<(256 * 128 + 255) / 256, 256>>>(sa_fcw, 256, 256, WH + WO_SAF, WL + WO_SAF);
    pack_w_kernel<<<(256 * 192 + 255) / 256, 256>>>(ms_w1,  384, 256, WH + WO_MS1, WL + WO_MS1);
    pack_w_kernel<<<(256 * 128 + 255) / 256, 256>>>(ms_w2,  256, 256, WH + WO_MS2, WL + WO_MS2);
    pack_w_kernel<<<(256 * 128 + 255) / 256, 256>>>(ca_wq,  256, 256, WH + WO_CAQ, WL + WO_CAQ);
    pack_w_kernel<<<(256 * 128 + 255) / 256, 256>>>(ca_wk,  256, 256, WH + WO_CAK, WL + WO_CAK);
    pack_w_kernel<<<(256 * 128 + 255) / 256, 256>>>(ca_wv,  256, 256, WH + WO_CAV, WL + WO_CAV);
    pack_src_kernel<<<(BATCH * PKL + 255) / 256, 256>>>(src, srct);

    concat_kv_kernel<<<ELEMS / 4 / 256, 256>>>(seq, seqt);

    dim3 g2(2, NROWS / 128);
    // QKV projections: A = KV packed
    gemm_tc_kernel<<<g2, 256, SMEM_GEMM>>>(KVh, KVl, 128, PKL, KVh, KVl, PKL,
        WH + WO_SAQ, WL + WO_SAQ, 256, 256, nullptr, nullptr, 0, Qb, nullptr, nullptr);
    gemm_tc_kernel<<<g2, 256, SMEM_GEMM>>>(KVh, KVl, 128, PKL, KVh, KVl, PKL,
        WH + WO_SAK, WL + WO_SAK, 256, 256, nullptr, nullptr, 0, Kb, nullptr, nullptr);
    gemm_tc_kernel<<<g2, 256, SMEM_GEMM>>>(KVh, KVl, 128, PKL, KVh, KVl, PKL,
        WH + WO_SAV, WL + WO_SAV, 256, 256, nullptr, nullptr, 0, Vb, nullptr, nullptr);

    dim3 ga(2, BATCH);
    sa_attn_kernel<<<ga, 256, SMEM_ATTN>>>(Qb, Kb, Vb, MK, AOh, AOl);

    // fc: A = AO packed, residual KV fp32 -> FC fp32
    gemm_tc_kernel<<<g2, 256, SMEM_GEMM>>>(AOh, AOl, 128, PKL, AOh, AOl, PKL,
        WH + WO_SAF, WL + WO_SAF, 256, 256, sa_fcb, KV, 0, FC, nullptr, nullptr);
    ln_kernel<<<NROWS / 8, 256>>>(FC, sa_lng, sa_lnb, SAh, SAl);

    // ms1: A1 = SA packed (kp<128), A2 = seq = KV packed cols 0..63 -> H1 packed only
    gemm_tc_kernel<<<g2, 256, SMEM_GEMM>>>(SAh, SAl, 128, PKL, KVh, KVl, PKL,
        WH + WO_MS1, WL + WO_MS1, 384, 256, ms_b1, nullptr, 1, nullptr, H1h, H1l);
    // ms2: A = H1 packed -> KC packed only
    gemm_tc_kernel<<<g2, 256, SMEM_GEMM>>>(H1h, H1l, 128, PKL, H1h, H1l, PKL,
        WH + WO_MS2, WL + WO_MS2, 256, 256, ms_b2, nullptr, 0, nullptr, KCh, KCl);

    // ca K/V projections: A = KC packed -> fp32
    gemm_tc_kernel<<<g2, 256, SMEM_GEMM>>>(KCh, KCl, 128, PKL, KCh, KCl, PKL,
        WH + WO_CAK, WL + WO_CAK, 256, 256, nullptr, nullptr, 0, KH, nullptr, nullptr);
    gemm_tc_kernel<<<g2, 256, SMEM_GEMM>>>(KCh, KCl, 128, PKL, KCh, KCl, PKL,
        WH + WO_CAV, WL + WO_CAV, 256, 256, nullptr, nullptr, 0, VH, nullptr, nullptr);

    // ca Q projection: A = SRC packed (M=1024)
    dim3 gq(2, BATCH / 128);
    gemm_tc_kernel<<<gq, 256, SMEM_GEMM>>>(SRCh, SRCl, 128, PKL, SRCh, SRCl, PKL,
        WH + WO_CAQ, WL + WO_CAQ, 256, 256, nullptr, nullptr, 0, QH, nullptr, nullptr);

    ca_kernel<<<BATCH, 256>>>(QH, KH, VH, MK,
                              ca_fcw, ca_fcb, ca_lng, ca_lnb,
                              src, srct, mg_w1, mg_b1, mg_w2, mg_b2,
                              out, out + (long)BATCH * 128);
}

// round 10
// speedup vs baseline: 1.1361x; 1.1361x over previous
#include <cuda_runtime.h>
#include <cuda_bf16.h>
#include <math.h>

#define BATCH  1024
#define SEQN   128
#define DMODEL 256
#define NROWS  (BATCH*SEQN)            // 131072
#define ELEMS  (BATCH*SEQN*DMODEL)     // 33554432
#define SST    132                     // padded smem row stride (floats)

// bf16 GEMM smem layout, u32 units. Row stride = 20 u32 (32 bf16 + pad) = 80 B.
#define RSTR 20
#define UA_H 0
#define UA_L (128*RSTR)
#define UB_H (2*128*RSTR)
#define UB_L (3*128*RSTR)
#define SM_GEMM_U32 (4*128*RSTR)     // 10240 u32 = 40960 B

// sa_attn smem layout (u32 units). Row stride 68 u32 (64 + 4 pad).
#define QSTR 68
#define OQH 0
#define OQL (128*QSTR)               // 8704
#define OKH (2*128*QSTR)             // 17408
#define OKL (3*128*QSTR)             // 26112
#define OPT (4*128*QSTR)             // 34816 : sPt float region (128*SST floats)
#define SM_ATTN_U32 (4*128*QSTR + 128*SST)   // 51712 u32 = 206848 B
// O-phase reuse: PH=OQH, PL=OQL, VH=OKH, VL=OKL

// ---------------- scratch ----------------
__device__ float g_KV[ELEMS];
__device__ float g_Q [ELEMS];
__device__ float g_K [ELEMS];
__device__ float g_V [ELEMS];
__device__ float g_AO[ELEMS];
__device__ float g_FC[ELEMS];
__device__ float g_SA[ELEMS];
__device__ float g_H1[ELEMS];
__device__ float g_KC[ELEMS];
__device__ float g_KH[ELEMS];
__device__ float g_VH[ELEMS];
__device__ float g_QH[BATCH*DMODEL];
__device__ unsigned char g_mask8[NROWS];
__device__ int g_mask_mode;

// ---------------- bf16 helpers ----------------
__device__ __forceinline__ unsigned pack_bf16x2(float lo, float hi) {
    unsigned r;
    asm("cvt.rn.bf16x2.f32 %0, %1, %2;" : "=r"(r) : "f"(hi), "f"(lo));
    return r;
}
__device__ __forceinline__ float lo_bf16f(unsigned u) { return __uint_as_float(u << 16); }
__device__ __forceinline__ float hi_bf16f(unsigned u) { return __uint_as_float(u & 0xFFFF0000u); }
__device__ __forceinline__ void split_pair(float f0, float f1, unsigned& h, unsigned& l) {
    h = pack_bf16x2(f0, f1);
    l = pack_bf16x2(f0 - lo_bf16f(h), f1 - hi_bf16f(h));
}
__device__ __forceinline__ void mma_bf16(float* d, const unsigned* a, const unsigned* b) {
    asm volatile(
        "mma.sync.aligned.m16n8k16.row.col.f32.bf16.bf16.f32 "
        "{%0,%1,%2,%3}, {%4,%5,%6,%7}, {%8,%9}, {%0,%1,%2,%3};\n"
        : "+f"(d[0]), "+f"(d[1]), "+f"(d[2]), "+f"(d[3])
        : "r"(a[0]), "r"(a[1]), "r"(a[2]), "r"(a[3]),
          "r"(b[0]), "r"(b[1]));
}

// ---------------- mask dtype detection + normalization ----------------
__global__ void detect_mask_kernel(const void* mask) {
    if (threadIdx.x == 0 && blockIdx.x == 0) {
        const unsigned* p = (const unsigned*)mask;
        int mode = 1;
        for (int i = 0; i < 1024; i++) {
            unsigned v = p[i];
            if (v == 0x3F800000u) { mode = 2; break; }
            if (v > 1u) { mode = 0; break; }
        }
        g_mask_mode = mode;
    }
}

__global__ __launch_bounds__(256) void norm_mask_kernel(const void* mask) {
    int i = blockIdx.x * 256 + threadIdx.x;
    if (i >= NROWS) return;
    int mode = g_mask_mode;
    unsigned char m;
    if (mode == 0)      m = (((const unsigned char*)mask)[i] != 0);
    else if (mode == 1) m = (((const int*)mask)[i] != 0);
    else                m = (((const float*)mask)[i] != 0.f);
    g_mask8[i] = m;
}

// ---------------- concat([seq, seq_t], -1) -> KV ----------------
__global__ __launch_bounds__(256) void concat_kv_kernel(
    const float* __restrict__ seq, const float* __restrict__ seqt)
{
    long i4 = (long)blockIdx.x * 256 + threadIdx.x;
    if (i4 >= (long)ELEMS / 4) return;
    long row = i4 >> 6;
    int  c4  = (int)(i4 & 63);
    float4 v;
    if (c4 < 32) v = ((const float4*)(seq  + row * 128))[c4];
    else         v = ((const float4*)(seqt + row * 128))[c4 - 32];
    ((float4*)(g_KV + row * 256))[c4] = v;
}

// ---------------- 3xBF16 tensor-core GEMM (m16n8k16, direct fragment LDS) ----------------
// (identical to R8 proven kernel)
__global__ __launch_bounds__(256, 2) void gemm_tc_kernel(
    const float* __restrict__ A1, int K1, int lda1,
    const float* __restrict__ A2, int lda2,
    const float* __restrict__ W, int Ktot, int Ncols,
    const float* __restrict__ bias,
    const float* __restrict__ res,
    int relu,
    float* __restrict__ C)
{
    extern __shared__ unsigned su[];
    unsigned* sAh = su + UA_H;
    unsigned* sAl = su + UA_L;
    unsigned* sBh = su + UB_H;
    unsigned* sBl = su + UB_L;

    const int tid  = threadIdx.x;
    const int warp = tid >> 5, lane = tid & 31;
    const int wm = warp & 3, wn = warp >> 2;
    const int group = lane >> 2, tig = lane & 3;
    const long m0 = (long)blockIdx.y * 128;
    const int  n0 = blockIdx.x * 128;
    const int wmb = wm * 32;
    const int wnb = wn * 64;

    float acc[2][8][4];
#pragma unroll
    for (int mi = 0; mi < 2; mi++)
#pragma unroll
        for (int ni = 0; ni < 8; ni++)
#pragma unroll
            for (int q = 0; q < 4; q++) acc[mi][ni][q] = 0.f;

    const int nk = Ktot / 32;

    for (int ck = 0; ck < nk; ck++) {
        const int k0 = ck * 32;
        if (ck > 0) __syncthreads();

#pragma unroll
        for (int i = 0; i < 4; i++) {
            int f4 = tid + i * 256;
            int row = f4 >> 3, c = (f4 & 7) * 4;
            const float* ap = (k0 < K1) ? (A1 + (m0 + row) * (long)lda1 + k0 + c)
                                        : (A2 + (m0 + row) * (long)lda2 + (k0 - K1) + c);
            float4 v = *(const float4*)ap;
            unsigned h0, l0, h1, l1;
            split_pair(v.x, v.y, h0, l0);
            split_pair(v.z, v.w, h1, l1);
            int ui = row * RSTR + (c >> 1);
            *(uint2*)&sAh[ui] = make_uint2(h0, h1);
            *(uint2*)&sAl[ui] = make_uint2(l0, l1);
        }
#pragma unroll
        for (int i = 0; i < 4; i++) {
            int task = tid + i * 256;
            int n  = task & 127;
            int kq = task >> 7;
            const float* wp = W + (long)(k0 + kq * 4) * Ncols + n0 + n;
            float f0 = wp[0];
            float f1 = wp[Ncols];
            float f2 = wp[2 * Ncols];
            float f3 = wp[3 * Ncols];
            unsigned h0, l0, h1, l1;
            split_pair(f0, f1, h0, l0);
            split_pair(f2, f3, h1, l1);
            int ui = n * RSTR + kq * 2;
            *(uint2*)&sBh[ui] = make_uint2(h0, h1);
            *(uint2*)&sBl[ui] = make_uint2(l0, l1);
        }
        __syncthreads();

#pragma unroll
        for (int ks = 0; ks < 2; ks++) {
            const int kb8 = ks * 8;
            unsigned ah[2][4], al[2][4];
#pragma unroll
            for (int mi = 0; mi < 2; mi++) {
                int r = wmb + mi * 16 + group;
                int i0 = r * RSTR + kb8 + tig;
                int i1 = (r + 8) * RSTR + kb8 + tig;
                ah[mi][0] = sAh[i0];
                ah[mi][1] = sAh[i1];
                ah[mi][2] = sAh[i0 + 4];
                ah[mi][3] = sAh[i1 + 4];
                al[mi][0] = sAl[i0];
                al[mi][1] = sAl[i1];
                al[mi][2] = sAl[i0 + 4];
                al[mi][3] = sAl[i1 + 4];
            }
#pragma unroll
            for (int nt = 0; nt < 8; nt++) {
                int nrow = wnb + nt * 8 + group;
                int bi = nrow * RSTR + kb8 + tig;
                unsigned bh[2], bl[2];
                bh[0] = sBh[bi];
                bh[1] = sBh[bi + 4];
                bl[0] = sBl[bi];
                bl[1] = sBl[bi + 4];
#pragma unroll
                for (int mi = 0; mi < 2; mi++) {
                    mma_bf16(acc[mi][nt], ah[mi], bh);
                    mma_bf16(acc[mi][nt], al[mi], bh);
                    mma_bf16(acc[mi][nt], ah[mi], bl);
                }
            }
        }
    }

#pragma unroll
    for (int mi = 0; mi < 2; mi++) {
        long gm = m0 + wmb + mi * 16 + group;
#pragma unroll
        for (int ni = 0; ni < 8; ni++) {
            int gc = n0 + wnb + ni * 8 + 2 * tig;
            float v0 = acc[mi][ni][0], v1 = acc[mi][ni][1];
            float v2 = acc[mi][ni][2], v3 = acc[mi][ni][3];
            if (bias) {
                float b0 = bias[gc], b1 = bias[gc + 1];
                v0 += b0; v1 += b1; v2 += b0; v3 += b1;
            }
            if (res) {
                float2 r0 = *(const float2*)(res + gm * Ncols + gc);
                float2 r1 = *(const float2*)(res + (gm + 8) * Ncols + gc);
                v0 += r0.x; v1 += r0.y; v2 += r1.x; v3 += r1.y;
            }
            if (relu) {
                v0 = fmaxf(v0, 0.f); v1 = fmaxf(v1, 0.f);
                v2 = fmaxf(v2, 0.f); v3 = fmaxf(v3, 0.f);
            }
            *(float2*)(C + gm * Ncols + gc)       = make_float2(v0, v1);
            *(float2*)(C + (gm + 8) * Ncols + gc) = make_float2(v2, v3);
        }
    }
}

// ---------------- self-attention: full bf16 tensor-core (S and O phases) ----------------
__global__ __launch_bounds__(256) void sa_attn_kernel(
    const float* __restrict__ Q, const float* __restrict__ K, const float* __restrict__ V,
    const unsigned char* __restrict__ mask, float* __restrict__ O)
{
    extern __shared__ unsigned su[];
    float* sPt = (float*)(su + OPT);
    __shared__ unsigned char smask[128];

    const int h = blockIdx.x, b = blockIdx.y;
    const int tid = threadIdx.x;
    const int warp = tid >> 5, lane = tid & 31;
    const int group = lane >> 2, tig = lane & 3;
    const float* Qp = Q + ((long)b * SEQN) * DMODEL + h * 128;
    const float* Kp = K + ((long)b * SEQN) * DMODEL + h * 128;
    const float* Vp = V + ((long)b * SEQN) * DMODEL + h * 128;
    const float invs = 0.0883883476483184f;  // 1/sqrt(128)

    const int wm = warp & 3;
    const int wmb = wm * 32, wnb = (warp >> 2) * 64;

    if (tid < 128) smask[tid] = mask[(long)b * SEQN + tid];
    // ---- load + pack Q(scaled), K -> hi/lo [row][kp] ----
    for (int idx = tid; idx < 128 * 32; idx += 256) {
        int r = idx >> 5;
        int c = (idx & 31) << 2;
        int ui = r * QSTR + (c >> 1);
        float4 qv = *(const float4*)(Qp + (long)r * DMODEL + c);
        qv.x *= invs; qv.y *= invs; qv.z *= invs; qv.w *= invs;
        unsigned h0, l0, h1, l1;
        split_pair(qv.x, qv.y, h0, l0);
        split_pair(qv.z, qv.w, h1, l1);
        *(uint2*)&su[OQH + ui] = make_uint2(h0, h1);
        *(uint2*)&su[OQL + ui] = make_uint2(l0, l1);
        float4 kv = *(const float4*)(Kp + (long)r * DMODEL + c);
        split_pair(kv.x, kv.y, h0, l0);
        split_pair(kv.z, kv.w, h1, l1);
        *(uint2*)&su[OKH + ui] = make_uint2(h0, h1);
        *(uint2*)&su[OKL + ui] = make_uint2(l0, l1);
    }
    __syncthreads();

    // ---- S = Qs · K^T (3xbf16, 8 resident k-steps) ----
    {
        float acc[2][8][4];
#pragma unroll
        for (int mi = 0; mi < 2; mi++)
#pragma unroll
            for (int ni = 0; ni < 8; ni++)
#pragma unroll
                for (int q = 0; q < 4; q++) acc[mi][ni][q] = 0.f;

#pragma unroll
        for (int ks = 0; ks < 8; ks++) {
            const int kb8 = ks * 8;
            unsigned ah[2][4], al[2][4];
#pragma unroll
            for (int mi = 0; mi < 2; mi++) {
                int r = wmb + mi * 16 + group;
                int i0 = r * QSTR + kb8 + tig;
                int i1 = (r + 8) * QSTR + kb8 + tig;
                ah[mi][0] = su[OQH + i0];
                ah[mi][1] = su[OQH + i1];
                ah[mi][2] = su[OQH + i0 + 4];
                ah[mi][3] = su[OQH + i1 + 4];
                al[mi][0] = su[OQL + i0];
                al[mi][1] = su[OQL + i1];
                al[mi][2] = su[OQL + i0 + 4];
                al[mi][3] = su[OQL + i1 + 4];
            }
#pragma unroll
            for (int nt = 0; nt < 8; nt++) {
                int nrow = wnb + nt * 8 + group;
                int bi = nrow * QSTR + kb8 + tig;
                unsigned bh[2], bl[2];
                bh[0] = su[OKH + bi];
                bh[1] = su[OKH + bi + 4];
                bl[0] = su[OKL + bi];
                bl[1] = su[OKL + bi + 4];
#pragma unroll
                for (int mi = 0; mi < 2; mi++) {
                    mma_bf16(acc[mi][nt], ah[mi], bh);
                    mma_bf16(acc[mi][nt], al[mi], bh);
                    mma_bf16(acc[mi][nt], ah[mi], bl);
                }
            }
        }
        // scatter to sPt[key][q]
#pragma unroll
        for (int mi = 0; mi < 2; mi++) {
            int gm0 = wmb + mi * 16 + group;
#pragma unroll
            for (int ni = 0; ni < 8; ni++) {
                int gc0 = wnb + ni * 8 + 2 * tig;
                sPt[gc0 * SST + gm0]           = acc[mi][ni][0];
                sPt[(gc0 + 1) * SST + gm0]     = acc[mi][ni][1];
                sPt[gc0 * SST + gm0 + 8]       = acc[mi][ni][2];
                sPt[(gc0 + 1) * SST + gm0 + 8] = acc[mi][ni][3];
            }
        }
    }
    __syncthreads();

    // ---- softmax over keys (per query row r), mask applied ----
    for (int r = warp; r < 128; r += 8) {
        float vv[4];
        float mx = -1e30f;
#pragma unroll
        for (int q = 0; q < 4; q++) {
            int c = lane + q * 32;
            float s = sPt[c * SST + r];
            if (smask[c]) s = -1e10f;
            vv[q] = s; mx = fmaxf(mx, s);
        }
#pragma unroll
        for (int o = 16; o > 0; o >>= 1) mx = fmaxf(mx, __shfl_xor_sync(0xffffffffu, mx, o));
        float sum = 0.f;
#pragma unroll
        for (int q = 0; q < 4; q++) { vv[q] = expf(vv[q] - mx); sum += vv[q]; }
#pragma unroll
        for (int o = 16; o > 0; o >>= 1) sum += __shfl_xor_sync(0xffffffffu, sum, o);
        float rs = 1.f / sum;
#pragma unroll
        for (int q = 0; q < 4; q++) sPt[(lane + q * 32) * SST + r] = vv[q] * rs;
    }
    __syncthreads();

    // ---- pack P [q][kp] into PH/PL (reuse Q region); pack V^T [d][kp] into VH/VL (reuse K region) ----
    for (int idx = tid; idx < 128 * 64; idx += 256) {
        int q = idx >> 6, kp = idx & 63;
        float p0 = sPt[(2 * kp) * SST + q];
        float p1 = sPt[(2 * kp + 1) * SST + q];
        unsigned hh, ll;
        split_pair(p0, p1, hh, ll);
        su[OQH + q * QSTR + kp] = hh;
        su[OQL + q * QSTR + kp] = ll;
    }
    for (int idx = tid; idx < 64 * 32; idx += 256) {
        int kplow = idx & 15;
        int rest  = idx >> 4;
        int c4 = rest & 31;
        int kp = (rest >> 5) * 16 + kplow;
        int c = c4 * 4;
        float4 v0 = *(const float4*)(Vp + (long)(2 * kp) * DMODEL + c);
        float4 v1 = *(const float4*)(Vp + (long)(2 * kp + 1) * DMODEL + c);
        unsigned hh, ll;
        split_pair(v0.x, v1.x, hh, ll);
        su[OKH + (c + 0) * QSTR + kp] = hh; su[OKL + (c + 0) * QSTR + kp] = ll;
        split_pair(v0.y, v1.y, hh, ll);
        su[OKH + (c + 1) * QSTR + kp] = hh; su[OKL + (c + 1) * QSTR + kp] = ll;
        split_pair(v0.z, v1.z, hh, ll);
        su[OKH + (c + 2) * QSTR + kp] = hh; su[OKL + (c + 2) * QSTR + kp] = ll;
        split_pair(v0.w, v1.w, hh, ll);
        su[OKH + (c + 3) * QSTR + kp] = hh; su[OKL + (c + 3) * QSTR + kp] = ll;
    }
    __syncthreads();

    // ---- O = P · V (3xbf16, 8 resident k-steps over keys) ----
    {
        float acc[2][8][4];
#pragma unroll
        for (int mi = 0; mi < 2; mi++)
#pragma unroll
            for (int ni = 0; ni < 8; ni++)
#pragma unroll
                for (int q = 0; q < 4; q++) acc[mi][ni][q] = 0.f;

#pragma unroll
        for (int ks = 0; ks < 8; ks++) {
            const int kb8 = ks * 8;
            unsigned ah[2][4], al[2][4];
#pragma unroll
            for (int mi = 0; mi < 2; mi++) {
                int r = wmb + mi * 16 + group;
                int i0 = r * QSTR + kb8 + tig;
                int i1 = (r + 8) * QSTR + kb8 + tig;
                ah[mi][0] = su[OQH + i0];
                ah[mi][1] = su[OQH + i1];
                ah[mi][2] = su[OQH + i0 + 4];
                ah[mi][3] = su[OQH + i1 + 4];
                al[mi][0] = su[OQL + i0];
                al[mi][1] = su[OQL + i1];
                al[mi][2] = su[OQL + i0 + 4];
                al[mi][3] = su[OQL + i1 + 4];
            }
#pragma unroll
            for (int nt = 0; nt < 8; nt++) {
                int nrow = wnb + nt * 8 + group;
                int bi = nrow * QSTR + kb8 + tig;
                unsigned bh[2], bl[2];
                bh[0] = su[OKH + bi];
                bh[1] = su[OKH + bi + 4];
                bl[0] = su[OKL + bi];
                bl[1] = su[OKL + bi + 4];
#pragma unroll
                for (int mi = 0; mi < 2; mi++) {
                    mma_bf16(acc[mi][nt], ah[mi], bh);
                    mma_bf16(acc[mi][nt], al[mi], bh);
                    mma_bf16(acc[mi][nt], ah[mi], bl);
                }
            }
        }

        // write O fp32
        float* Op = O + ((long)b * SEQN) * DMODEL + h * 128;
#pragma unroll
        for (int mi = 0; mi < 2; mi++) {
            int gm = wmb + mi * 16 + group;
#pragma unroll
            for (int nt = 0; nt < 8; nt++) {
                int gc = wnb + nt * 8 + 2 * tig;
                *(float2*)(Op + (long)gm * DMODEL + gc)       = make_float2(acc[mi][nt][0], acc[mi][nt][1]);
                *(float2*)(Op + (long)(gm + 8) * DMODEL + gc) = make_float2(acc[mi][nt][2], acc[mi][nt][3]);
            }
        }
    }
}

// ---------------- LayerNorm over 256, warp per row ----------------
__global__ __launch_bounds__(256) void ln_kernel(
    const float* __restrict__ X, const float* __restrict__ gw,
    const float* __restrict__ bw, float* __restrict__ Y)
{
    long row = (long)blockIdx.x * 8 + (threadIdx.x >> 5);
    int lane = threadIdx.x & 31;
    const float* xp = X + row * 256 + lane * 8;
    float4 a = *(const float4*)xp;
    float4 b = *(const float4*)(xp + 4);
    float s = a.x + a.y + a.z + a.w + b.x + b.y + b.z + b.w;
#pragma unroll
    for (int o = 16; o > 0; o >>= 1) s += __shfl_xor_sync(0xffffffffu, s, o);
    float mean = s * 0.00390625f;
    float q = 0.f;
    q += (a.x - mean) * (a.x - mean); q += (a.y - mean) * (a.y - mean);
    q += (a.z - mean) * (a.z - mean); q += (a.w - mean) * (a.w - mean);
    q += (b.x - mean) * (b.x - mean); q += (b.y - mean) * (b.y - mean);
    q += (b.z - mean) * (b.z - mean); q += (b.w - mean) * (b.w - mean);
#pragma unroll
    for (int o = 16; o > 0; o >>= 1) q += __shfl_xor_sync(0xffffffffu, q, o);
    float rstd = rsqrtf(q * 0.00390625f + 1e-5f);
    int c = lane * 8;
    float4 g0 = *(const float4*)(gw + c), g1 = *(const float4*)(gw + c + 4);
    float4 b0 = *(const float4*)(bw + c), b1 = *(const float4*)(bw + c + 4);
    float4 o0, o1;
    o0.x = (a.x - mean) * rstd * g0.x + b0.x;
    o0.y = (a.y - mean) * rstd * g0.y + b0.y;
    o0.z = (a.z - mean) * rstd * g0.z + b0.z;
    o0.w = (a.w - mean) * rstd * g0.w + b0.w;
    o1.x = (b.x - mean) * rstd * g1.x + b1.x;
    o1.y = (b.y - mean) * rstd * g1.y + b1.y;
    o1.z = (b.z - mean) * rstd * g1.z + b1.z;
    o1.w = (b.w - mean) * rstd * g1.w + b1.w;
    *(float4*)(Y + row * 256 + c)     = o0;
    *(float4*)(Y + row * 256 + c + 4) = o1;
}

// ---------------- cross-attention + fc + LN + output MLP ----------------
__global__ __launch_bounds__(256) void ca_kernel(
    const float* __restrict__ QH, const float* __restrict__ KH, const float* __restrict__ VH,
    const unsigned char* __restrict__ mask,
    const float* __restrict__ fcw, const float* __restrict__ fcb,
    const float* __restrict__ lng, const float* __restrict__ lnb,
    const float* __restrict__ src, const float* __restrict__ srct,
    const float* __restrict__ w1, const float* __restrict__ b1,
    const float* __restrict__ w2, const float* __restrict__ b2,
    float* __restrict__ out_vec, float* __restrict__ out_attn)
{
    const int b = blockIdx.x;
    const int tid = threadIdx.x;
    __shared__ float s_q[256], s_p[256], s_o[256], s_y[256], s_h[128], s_red[16];

    s_q[tid] = QH[(long)b * 256 + tid];
    __syncthreads();

    const int h = tid >> 7, k = tid & 127;
    const int lane = tid & 31, warp = tid >> 5;

    const float* krow = KH + ((long)b * 128 + k) * 256 + h * 128;
    float s = 0.f;
#pragma unroll 8
    for (int d = 0; d < 128; d += 4) {
        float4 kv = *(const float4*)(krow + d);
        s += s_q[h * 128 + d + 0] * kv.x + s_q[h * 128 + d + 1] * kv.y
           + s_q[h * 128 + d + 2] * kv.z + s_q[h * 128 + d + 3] * kv.w;
    }
    s *= 0.0883883476483184f;
    if (mask[(long)b * 128 + k]) s = -1e10f;

    float mx = s;
#pragma unroll
    for (int o = 16; o > 0; o >>= 1) mx = fmaxf(mx, __shfl_xor_sync(0xffffffffu, mx, o));
    if (lane == 0) s_red[warp] = mx;
    __syncthreads();
    mx = fmaxf(fmaxf(s_red[h * 4 + 0], s_red[h * 4 + 1]),
               fmaxf(s_red[h * 4 + 2], s_red[h * 4 + 3]));
    float e = expf(s - mx);
    float sum = e;
#pragma unroll
    for (int o = 16; o > 0; o >>= 1) sum += __shfl_xor_sync(0xffffffffu, sum, o);
    if (lane == 0) s_red[8 + warp] = sum;
    __syncthreads();
    sum = s_red[8 + h * 4 + 0] + s_red[8 + h * 4 + 1] + s_red[8 + h * 4 + 2] + s_red[8 + h * 4 + 3];
    float p = e / sum;
    s_p[tid] = p;
    out_attn[((long)h * BATCH + b) * 128 + k] = p;
    __syncthreads();

    const int d = tid & 127;
    float o = 0.f;
#pragma unroll 8
    for (int kk = 0; kk < 128; kk++)
        o += s_p[h * 128 + kk] * VH[((long)b * 128 + kk) * 256 + h * 128 + d];
    s_o[tid] = o;
    __syncthreads();

    float y = fcb[tid];
    for (int i = 0; i < 256; i++) y += s_o[i] * fcw[i * 256 + tid];
    y += (tid < 128) ? src[(long)b * 128 + tid] : srct[(long)b * 128 + tid - 128];

    float t = y;
#pragma unroll
    for (int ofs = 16; ofs > 0; ofs >>= 1) t += __shfl_xor_sync(0xffffffffu, t, ofs);
    if (lane == 0) s_red[warp] = t;
    __syncthreads();
    float mean = (s_red[0] + s_red[1] + s_red[2] + s_red[3] +
                  s_red[4] + s_red[5] + s_red[6] + s_red[7]) * 0.00390625f;
    float dv = y - mean;
    t = dv * dv;
#pragma unroll
    for (int ofs = 16; ofs > 0; ofs >>= 1) t += __shfl_xor_sync(0xffffffffu, t, ofs);
    if (lane == 0) s_red[8 + warp] = t;
    __syncthreads();
    float var = (s_red[8] + s_red[9] + s_red[10] + s_red[11] +
                 s_red[12] + s_red[13] + s_red[14] + s_red[15]) * 0.00390625f;
    float rstd = rsqrtf(var + 1e-5f);
    s_y[tid] = dv * rstd * lng[tid] + lnb[tid];
    __syncthreads();

    if (tid < 128) {
        float hh = b1[tid];
        for (int i = 0; i < 256; i++) hh += s_y[i] * w1[i * 128 + tid];
        for (int i = 0; i < 128; i++) hh += src[(long)b * 128 + i] * w1[(256 + i) * 128 + tid];
        s_h[tid] = fmaxf(hh, 0.f);
    }
    __syncthreads();
    if (tid < 128) {
        float oo = b2[tid];
        for (int i = 0; i < 128; i++) oo += s_h[i] * w2[i * 128 + tid];
        out_vec[(long)b * 128 + tid] = oo;
    }
}

// ---------------- host ----------------
static float* sym_addr(const void* s) {
    void* p = nullptr;
    cudaGetSymbolAddress(&p, s);
    return (float*)p;
}

extern "C" void kernel_launch(void* const* d_in, const int* in_sizes, int n_in,
                              void* d_out, int out_size)
{
    const float* src   = (const float*)d_in[0];
    const float* srct  = (const float*)d_in[1];
    const float* seq   = (const float*)d_in[2];
    const float* seqt  = (const float*)d_in[3];
    const void*  maskraw = d_in[4];

    const float *sa_wq, *sa_wk, *sa_wv, *sa_fcw, *sa_fcb, *sa_lng, *sa_lnb;
    const float *ms_w1, *ms_b1, *ms_w2, *ms_b2;
    const float *ca_wq, *ca_wk, *ca_wv, *ca_fcw, *ca_fcb, *ca_lng, *ca_lnb;
    const float *mg_w1, *mg_b1, *mg_w2, *mg_b2;

    bool dict_order = (in_sizes[10] == 98304);
    if (dict_order) {
        sa_wq  = (const float*)d_in[5];
        sa_wk  = (const float*)d_in[6];
        sa_wv  = (const float*)d_in[7];
        sa_fcw = (const float*)d_in[8];
        sa_fcb = (const float*)d_in[9];
        ms_w1  = (const float*)d_in[10];
        ms_b1  = (const float*)d_in[11];
        ms_w2  = (const float*)d_in[12];
        ms_b2  = (const float*)d_in[13];
        ca_wq  = (const float*)d_in[14];
        ca_wk  = (const float*)d_in[15];
        ca_wv  = (const float*)d_in[16];
        ca_fcw = (const float*)d_in[17];
        ca_fcb = (const float*)d_in[18];
        mg_w1  = (const float*)d_in[19];
        mg_b1  = (const float*)d_in[20];
        mg_w2  = (const float*)d_in[21];
        mg_b2  = (const float*)d_in[22];
        sa_lng = (const float*)d_in[23];
        sa_lnb = (const float*)d_in[24];
        ca_lng = (const float*)d_in[25];
        ca_lnb = (const float*)d_in[26];
    } else {
        sa_wq  = (const float*)d_in[5];
        sa_wk  = (const float*)d_in[6];
        sa_wv  = (const float*)d_in[7];
        sa_fcw = (const float*)d_in[8];
        sa_fcb = (const float*)d_in[9];
        sa_lng = (const float*)d_in[10];
        sa_lnb = (const float*)d_in[11];
        ms_w1  = (const float*)d_in[12];
        ms_b1  = (const float*)d_in[13];
        ms_w2  = (const float*)d_in[14];
        ms_b2  = (const float*)d_in[15];
        ca_wq  = (const float*)d_in[16];
        ca_wk  = (const float*)d_in[17];
        ca_wv  = (const float*)d_in[18];
        ca_fcw = (const float*)d_in[19];
        ca_fcb = (const float*)d_in[20];
        ca_lng = (const float*)d_in[21];
        ca_lnb = (const float*)d_in[22];
        mg_w1  = (const float*)d_in[23];
        mg_b1  = (const float*)d_in[24];
        mg_w2  = (const float*)d_in[25];
        mg_b2  = (const float*)d_in[26];
    }
    float* out = (float*)d_out;

    float* KV = sym_addr(g_KV);
    float* Qb = sym_addr(g_Q);
    float* Kb = sym_addr(g_K);
    float* Vb = sym_addr(g_V);
    float* AO = sym_addr(g_AO);
    float* FC = sym_addr(g_FC);
    float* SA = sym_addr(g_SA);
    float* H1 = sym_addr(g_H1);
    float* KC = sym_addr(g_KC);
    float* KH = sym_addr(g_KH);
    float* VH = sym_addr(g_VH);
    float* QH = sym_addr(g_QH);
    unsigned char* MK = (unsigned char*)sym_addr(g_mask8);

    const int SMEM_ATTN = SM_ATTN_U32 * 4;     // 206848 bytes
    cudaFuncSetAttribute(sa_attn_kernel, cudaFuncAttributeMaxDynamicSharedMemorySize, SMEM_ATTN);
    const int SMEM_GEMM = SM_GEMM_U32 * 4;     // 40960 bytes (2 CTAs/SM)
    cudaFuncSetAttribute(gemm_tc_kernel, cudaFuncAttributeMaxDynamicSharedMemorySize, SMEM_GEMM);

    detect_mask_kernel<<<1, 32>>>(maskraw);
    norm_mask_kernel<<<NROWS / 256, 256>>>(maskraw);

    concat_kv_kernel<<<ELEMS / 4 / 256, 256>>>(seq, seqt);

    dim3 g2(2, NROWS / 128);
    gemm_tc_kernel<<<g2, 256, SMEM_GEMM>>>(KV, 256, 256, nullptr, 0, sa_wq, 256, 256, nullptr, nullptr, 0, Qb);
    gemm_tc_kernel<<<g2, 256, SMEM_GEMM>>>(KV, 256, 256, nullptr, 0, sa_wk, 256, 256, nullptr, nullptr, 0, Kb);
    gemm_tc_kernel<<<g2, 256, SMEM_GEMM>>>(KV, 256, 256, nullptr, 0, sa_wv, 256, 256, nullptr, nullptr, 0, Vb);

    dim3 ga(2, BATCH);
    sa_attn_kernel<<<ga, 256, SMEM_ATTN>>>(Qb, Kb, Vb, MK, AO);

    gemm_tc_kernel<<<g2, 256, SMEM_GEMM>>>(AO, 256, 256, nullptr, 0, sa_fcw, 256, 256, sa_fcb, KV, 0, FC);
    ln_kernel<<<NROWS / 8, 256>>>(FC, sa_lng, sa_lnb, SA);

    gemm_tc_kernel<<<g2, 256, SMEM_GEMM>>>(SA, 256, 256, seq, 128, ms_w1, 384, 256, ms_b1, nullptr, 1, H1);
    gemm_tc_kernel<<<g2, 256, SMEM_GEMM>>>(H1, 256, 256, nullptr, 0, ms_w2, 256, 256, ms_b2, nullptr, 0, KC);

    gemm_tc_kernel<<<g2, 256, SMEM_GEMM>>>(KC, 256, 256, nullptr, 0, ca_wk, 256, 256, nullptr, nullptr, 0, KH);
    gemm_tc_kernel<<<g2, 256, SMEM_GEMM>>>(KC, 256, 256, nullptr, 0, ca_wv, 256, 256, nullptr, nullptr, 0, VH);

    dim3 gq(2, BATCH / 128);
    gemm_tc_kernel<<<gq, 256, SMEM_GEMM>>>(src, 128, 128, srct, 128, ca_wq, 256, 256, nullptr, nullptr, 0, QH);

    ca_kernel<<<BATCH, 256>>>(QH, KH, VH, MK,
                              ca_fcw, ca_fcb, ca_lng, ca_lnb,
                              src, srct, mg_w1, mg_b1, mg_w2, mg_b2,
                              out, out + (long)BATCH * 128);
}